// round 13
// baseline (speedup 1.0000x reference)
#include <cuda_runtime.h>
#include <cuda_bf16.h>
#include <cstdint>

// act_shift = log(1/(1-1e-4) - 1) in double, narrowed (matches numpy path).
#define ACT_SHIFT (-9.210240366976184)
#define LOG2E_D   (1.4426950408889634)

// Single-instruction MUFU paths.
__device__ __forceinline__ float ex2f(float x) {
    float r; asm("ex2.approx.ftz.f32 %0, %1;" : "=f"(r) : "f"(x)); return r;
}
__device__ __forceinline__ float rsqf(float x) {
    float r; asm("rsqrt.approx.ftz.f32 %0, %1;" : "=f"(r) : "f"(x)); return r;
}

// alpha = 1-(1+y)^{-1/2} = y*(1/2 - 3/8 y + 5/16 y^2 - 35/128 y^3 + 63/256 y^4)
__device__ __forceinline__ float alpha_poly(float y) {
    return y * fmaf(y, fmaf(y, fmaf(y, fmaf(y, 0.24609375f, -0.2734375f),
                                    0.3125f), -0.375f), 0.5f);
}

// first index i in [0,M) with ray_id[i] >= key  (ray_id sorted ascending)
__device__ __forceinline__ int lower_bound_i(const int* __restrict__ a, int M, int key) {
    int lo = 0, hi = M;
    while (lo < hi) {
        int mid = (lo + hi) >> 1;
        if (__ldg(a + mid) < key) lo = mid + 1; else hi = mid;
    }
    return lo;
}

// ---------------------------------------------------------------------------
// Single fused kernel: block = 8 rays. Threads 0..8 binary-search the 9 ray
// boundaries into smem (upper probe levels are L1/L2-resident since every
// block hits the same midpoints); then each warp runs the proven
// 160-element-tile product-domain segmented scan on its ray.
// ---------------------------------------------------------------------------
__global__ void __launch_bounds__(256)
fused_ray_kernel(const float* __restrict__ density,
                 const int* __restrict__ ray_id,
                 float* __restrict__ out_w,
                 float* __restrict__ out_ainv,
                 int Nrays, int M) {
    __shared__ int s_bound[9];

    int tid  = threadIdx.x;
    int lane = tid & 31;
    int wk   = tid >> 5;                       // warp index in block: 0..7
    int r0   = blockIdx.x * 8;                 // first ray of this block

    if (tid < 9) {
        int key = r0 + tid;
        if (key > Nrays) key = Nrays;          // clamp (generic tail)
        s_bound[tid] = lower_bound_i(ray_id, M, key);
    }
    __syncthreads();

    int warp_ray = r0 + wk;
    if (warp_ray >= Nrays) return;

    int start = s_bound[wk];
    int end   = s_bound[wk + 1];

    const float l2e  = (float)LOG2E_D;
    const float sl2e = (float)(ACT_SHIFT * LOG2E_D);

    int astart = start & ~3;                   // 4-aligned tile origin
    int lo     = start - astart;               // 0..3 head pad (lane 0)
    float carry = 1.0f;                        // running product of q = 1+y

    for (int abase = astart; abase < end; abase += 160) {
        // ---- Part 1: [abase, abase+128), 4/lane vectorized ----
        int i0 = abase + lane * 4;             // 4-aligned (160 % 4 == 0)
        int hi = end - i0;                     // j valid iff j < hi

        float d0 = 0.f, d1 = 0.f, d2 = 0.f, d3 = 0.f;
        if (i0 + 3 < M) {
            float4 v4 = *reinterpret_cast<const float4*>(density + i0);
            d0 = v4.x; d1 = v4.y; d2 = v4.z; d3 = v4.w;
        } else {
            if (i0     < M) d0 = density[i0];
            if (i0 + 1 < M) d1 = density[i0 + 1];
            if (i0 + 2 < M) d2 = density[i0 + 2];
            if (i0 + 3 < M) d3 = density[i0 + 3];
        }

        float y0 = (0 < hi) ? ex2f(fmaf(d0, l2e, sl2e)) : 0.0f;
        float y1 = (1 < hi) ? ex2f(fmaf(d1, l2e, sl2e)) : 0.0f;
        float y2 = (2 < hi) ? ex2f(fmaf(d2, l2e, sl2e)) : 0.0f;
        float y3 = (3 < hi) ? ex2f(fmaf(d3, l2e, sl2e)) : 0.0f;

        if (abase == astart && lane == 0) {    // head-alignment pad
            if (lo > 0) y0 = 0.0f;
            if (lo > 1) y1 = 0.0f;
            if (lo > 2) y2 = 0.0f;
        }

        float q0 = 1.0f + y0, q1 = 1.0f + y1, q2 = 1.0f + y2, q3 = 1.0f + y3;
        float P0 = q0;
        float P1 = P0 * q1;
        float P2 = P1 * q2;
        float P3 = P2 * q3;

        float v = P3;                          // warp product scan
        #pragma unroll
        for (int o = 1; o < 32; o <<= 1) {
            float u = __shfl_up_sync(0xFFFFFFFFu, v, o);
            if (lane >= o) v *= u;
        }
        float ve = __shfl_up_sync(0xFFFFFFFFu, v, 1);
        if (lane == 0) ve = 1.0f;
        float P128 = __shfl_sync(0xFFFFFFFFu, v, 31);

        float T = rsqf(carry * ve);

        float a0 = alpha_poly(y0);
        float a1 = alpha_poly(y1);
        float a2 = alpha_poly(y2);
        float a3 = alpha_poly(y3);

        float w0 = a0 * T;  T = fmaf(-T, a0, T);
        float w1 = a1 * T;  T = fmaf(-T, a1, T);
        float w2 = a2 * T;  T = fmaf(-T, a2, T);
        float w3 = a3 * T;

        if (i0 >= start && i0 + 4 <= end) {    // interior quad (common)
            *reinterpret_cast<float4*>(out_w + i0) = make_float4(w0, w1, w2, w3);
        } else {
            if (i0     >= start && 0 < hi) out_w[i0]     = w0;
            if (i0 + 1 >= start && 1 < hi) out_w[i0 + 1] = w1;
            if (i0 + 2 >= start && 2 < hi) out_w[i0 + 2] = w2;
            if (i0 + 3 >= start && 3 < hi) out_w[i0 + 3] = w3;
        }

        carry *= P128;                         // product up to abase+128

        // ---- Part 2: [abase+128, abase+160) — warp-uniform skip ----
        if (abase + 128 < end) {
            int i2 = abase + 128 + lane;       // i2 > start always
            bool v2ok = (i2 < end);
            float d4 = 0.0f;
            if (v2ok) d4 = density[i2];        // coalesced 32-wide
            float y4 = v2ok ? ex2f(fmaf(d4, l2e, sl2e)) : 0.0f;
            float q4 = 1.0f + y4;

            float s2 = q4;                     // second warp product scan
            #pragma unroll
            for (int o = 1; o < 32; o <<= 1) {
                float u = __shfl_up_sync(0xFFFFFFFFu, s2, o);
                if (lane >= o) s2 *= u;
            }
            float ve2 = __shfl_up_sync(0xFFFFFFFFu, s2, 1);
            if (lane == 0) ve2 = 1.0f;

            float T2 = rsqf(carry * ve2);
            float w4 = alpha_poly(y4) * T2;
            if (v2ok) out_w[i2] = w4;

            carry *= __shfl_sync(0xFFFFFFFFu, s2, 31);
        }
    }

    if (lane == 0) {
        out_ainv[warp_ray] = rsqf(carry);      // empty ray: carry==1 -> 1
    }
}

extern "C" void kernel_launch(void* const* d_in, const int* in_sizes, int n_in,
                              void* d_out, int out_size) {
    const float* density = (const float*)d_in[0];
    const int*   ray_id  = (const int*)d_in[1];
    int M = in_sizes[0];
    int Nrays = out_size - M;            // output = [weights(M) | alphainv_last(N)]
    if (Nrays < 0) Nrays = 0;

    float* out_w    = (float*)d_out;
    float* out_ainv = (float*)d_out + M;

    if (Nrays > 0) {
        int blocks = (Nrays + 7) / 8;    // 8 rays (warps) per block
        fused_ray_kernel<<<blocks, 256>>>(density, ray_id, out_w, out_ainv,
                                          Nrays, M);
    }
}

// round 16
// speedup vs baseline: 1.8688x; 1.8688x over previous
#include <cuda_runtime.h>
#include <cuda_bf16.h>
#include <cstdint>

// act_shift = log(1/(1-1e-4) - 1) in double, narrowed (matches numpy path).
#define ACT_SHIFT (-9.210240366976184)
#define LOG2E_D   (1.4426950408889634)

#define MAX_RAYS (1 << 20)
__device__ int g_ray_start[MAX_RAYS + 1];

// Single-instruction MUFU paths.
__device__ __forceinline__ float ex2f(float x) {
    float r; asm("ex2.approx.ftz.f32 %0, %1;" : "=f"(r) : "f"(x)); return r;
}
__device__ __forceinline__ float rsqf(float x) {
    float r; asm("rsqrt.approx.ftz.f32 %0, %1;" : "=f"(r) : "f"(x)); return r;
}

// alpha = 1-(1+y)^{-1/2} = y*(1/2 - 3/8 y + 5/16 y^2 - 35/128 y^3 + 63/256 y^4)
__device__ __forceinline__ float alpha_poly(float y) {
    return y * fmaf(y, fmaf(y, fmaf(y, fmaf(y, 0.24609375f, -0.2734375f),
                                    0.3125f), -0.375f), 0.5f);
}

// first index i in [0,M) with ray_id[i] >= key  (ray_id sorted ascending)
__device__ __forceinline__ int lower_bound_i(const int* __restrict__ a, int M, int key) {
    int lo = 0, hi = M;
    while (lo < hi) {
        int mid = (int)(((unsigned)lo + (unsigned)hi) >> 1);
        if (__ldg(a + mid) < key) lo = mid + 1; else hi = mid;
    }
    return lo;
}

// ---------------------------------------------------------------------------
// Pass 1: one thread per ray — binary search per boundary. All threads busy
// (contrast with the failed fused version's 9-of-256 + barrier). Consecutive
// lanes search consecutive keys: upper tree levels are broadcast L1/L2 hits,
// lower levels fan out into parallel-issued adjacent lines.
// ---------------------------------------------------------------------------
__global__ void find_starts_bs_kernel(const int* __restrict__ ray_id, int M, int Nrays) {
    int r = blockIdx.x * blockDim.x + threadIdx.x;
    if (r > Nrays) return;                     // inclusive: g_ray_start[Nrays] = M
    g_ray_start[r] = lower_bound_i(ray_id, M, r);
}

// ---------------------------------------------------------------------------
// Pass 2 (round-12 proven, unchanged): one warp per ray, 160-element tiles.
//   Part 1: 4 elems/lane (float4) over [abase, abase+128)
//   Part 2: 1 elem/lane (scalar) over [abase+128, abase+160),
//           SKIPPED (warp-uniform) when the ray ends inside part 1.
// Product-domain: y = e^{d+shift}, q = 1+y, T = rsq(prefix product),
// alpha = y*poly(y) (pure FMA).
// ---------------------------------------------------------------------------
__global__ void __launch_bounds__(256)
ray_scan_kernel(const float* __restrict__ density,
                float* __restrict__ out_w,
                float* __restrict__ out_ainv,
                int Nrays, int M) {
    int warp_id = (int)((blockIdx.x * (unsigned)blockDim.x + threadIdx.x) >> 5);
    int lane    = threadIdx.x & 31;
    if (warp_id >= Nrays) return;

    int start = g_ray_start[warp_id];
    int end   = g_ray_start[warp_id + 1];

    const float l2e  = (float)LOG2E_D;
    const float sl2e = (float)(ACT_SHIFT * LOG2E_D);

    int astart = start & ~3;                   // 4-aligned tile origin
    int lo     = start - astart;               // 0..3 head pad (lane 0)
    float carry = 1.0f;                        // running product of q = 1+y

    for (int abase = astart; abase < end; abase += 160) {
        // ---- Part 1: [abase, abase+128), 4/lane vectorized ----
        int i0 = abase + lane * 4;             // 4-aligned (160 % 4 == 0)
        int hi = end - i0;                     // j valid iff j < hi

        float d0 = 0.f, d1 = 0.f, d2 = 0.f, d3 = 0.f;
        if (i0 + 3 < M) {
            float4 v4 = *reinterpret_cast<const float4*>(density + i0);
            d0 = v4.x; d1 = v4.y; d2 = v4.z; d3 = v4.w;
        } else {
            if (i0     < M) d0 = density[i0];
            if (i0 + 1 < M) d1 = density[i0 + 1];
            if (i0 + 2 < M) d2 = density[i0 + 2];
            if (i0 + 3 < M) d3 = density[i0 + 3];
        }

        float y0 = (0 < hi) ? ex2f(fmaf(d0, l2e, sl2e)) : 0.0f;
        float y1 = (1 < hi) ? ex2f(fmaf(d1, l2e, sl2e)) : 0.0f;
        float y2 = (2 < hi) ? ex2f(fmaf(d2, l2e, sl2e)) : 0.0f;
        float y3 = (3 < hi) ? ex2f(fmaf(d3, l2e, sl2e)) : 0.0f;

        if (abase == astart && lane == 0) {    // head-alignment pad
            if (lo > 0) y0 = 0.0f;
            if (lo > 1) y1 = 0.0f;
            if (lo > 2) y2 = 0.0f;
        }

        float q0 = 1.0f + y0, q1 = 1.0f + y1, q2 = 1.0f + y2, q3 = 1.0f + y3;
        float P0 = q0;
        float P1 = P0 * q1;
        float P2 = P1 * q2;
        float P3 = P2 * q3;

        float v = P3;                          // warp product scan
        #pragma unroll
        for (int o = 1; o < 32; o <<= 1) {
            float u = __shfl_up_sync(0xFFFFFFFFu, v, o);
            if (lane >= o) v *= u;
        }
        float ve = __shfl_up_sync(0xFFFFFFFFu, v, 1);
        if (lane == 0) ve = 1.0f;
        float P128 = __shfl_sync(0xFFFFFFFFu, v, 31);

        float T = rsqf(carry * ve);

        float a0 = alpha_poly(y0);
        float a1 = alpha_poly(y1);
        float a2 = alpha_poly(y2);
        float a3 = alpha_poly(y3);

        float w0 = a0 * T;  T = fmaf(-T, a0, T);
        float w1 = a1 * T;  T = fmaf(-T, a1, T);
        float w2 = a2 * T;  T = fmaf(-T, a2, T);
        float w3 = a3 * T;

        if (i0 >= start && i0 + 4 <= end) {    // interior quad (common)
            *reinterpret_cast<float4*>(out_w + i0) = make_float4(w0, w1, w2, w3);
        } else {
            if (i0     >= start && 0 < hi) out_w[i0]     = w0;
            if (i0 + 1 >= start && 1 < hi) out_w[i0 + 1] = w1;
            if (i0 + 2 >= start && 2 < hi) out_w[i0 + 2] = w2;
            if (i0 + 3 >= start && 3 < hi) out_w[i0 + 3] = w3;
        }

        carry *= P128;                         // product up to abase+128

        // ---- Part 2: [abase+128, abase+160) — warp-uniform skip ----
        if (abase + 128 < end) {
            int i2 = abase + 128 + lane;       // i2 > start always
            bool v2ok = (i2 < end);
            float d4 = 0.0f;
            if (v2ok) d4 = density[i2];        // coalesced 32-wide
            float y4 = v2ok ? ex2f(fmaf(d4, l2e, sl2e)) : 0.0f;
            float q4 = 1.0f + y4;

            float s2 = q4;                     // second warp product scan
            #pragma unroll
            for (int o = 1; o < 32; o <<= 1) {
                float u = __shfl_up_sync(0xFFFFFFFFu, s2, o);
                if (lane >= o) s2 *= u;
            }
            float ve2 = __shfl_up_sync(0xFFFFFFFFu, s2, 1);
            if (lane == 0) ve2 = 1.0f;

            float T2 = rsqf(carry * ve2);
            float w4 = alpha_poly(y4) * T2;
            if (v2ok) out_w[i2] = w4;

            carry *= __shfl_sync(0xFFFFFFFFu, s2, 31);
        }
    }

    if (lane == 0) {
        out_ainv[warp_id] = rsqf(carry);       // empty ray: carry==1 -> 1
    }
}

extern "C" void kernel_launch(void* const* d_in, const int* in_sizes, int n_in,
                              void* d_out, int out_size) {
    const float* density = (const float*)d_in[0];
    const int*   ray_id  = (const int*)d_in[1];
    int M = in_sizes[0];
    int Nrays = out_size - M;            // output = [weights(M) | alphainv_last(N)]
    if (Nrays < 0) Nrays = 0;
    if (Nrays > MAX_RAYS) Nrays = MAX_RAYS;

    float* out_w    = (float*)d_out;
    float* out_ainv = (float*)d_out + M;

    {
        int threads = 256;
        int blocks  = (Nrays + 1 + threads - 1) / threads;   // Nrays+1 searches
        find_starts_bs_kernel<<<blocks, threads>>>(ray_id, M, Nrays);
    }
    {
        int threads = 256;                       // 8 warps/block -> 8 rays/block
        long long total_threads = (long long)Nrays * 32;
        int blocks = (int)((total_threads + threads - 1) / threads);
        if (blocks > 0)
            ray_scan_kernel<<<blocks, threads>>>(density, out_w, out_ainv, Nrays, M);
    }
}